// round 1
// baseline (speedup 1.0000x reference)
#include <cuda_runtime.h>
#include <math.h>
#include <stdint.h>

#define B_ 16
#define C_ 80
#define N_ 22743          // 3*(19*19 + 38*38 + 76*76)
#define K_ 100
#define CELLS_ 7581       // 19*19 + 38*38 + 76*76
#define M_ (C_*K_)        // 8000

// ---------------- scratch (device globals; no allocations allowed) ----------
__device__ float g_boxes[B_*N_*4];                 // 5.8 MB
__device__ float g_scores[(size_t)B_*C_*N_];       // 116 MB, layout (B, C, N)
__device__ float g_top_s[B_*M_];                   // per-class top-100 scores
__device__ float g_top_b[B_*M_*4];                 // per-class top-100 boxes
__device__ float g_cand[B_*M_];                    // post-NMS candidate scores

__device__ __forceinline__ float sigmoidf_(float x) { return 1.0f/(1.0f+expf(-x)); }

// ---------------- stage 1: decode all 3 layers ------------------------------
__global__ void decode_kernel(const float* __restrict__ f0, const float* __restrict__ f1,
                              const float* __restrict__ f2, const float* __restrict__ anchors,
                              const float* __restrict__ imshape) {
    int tid = blockIdx.x * blockDim.x + threadIdx.x;
    if (tid >= B_*CELLS_) return;
    int b  = tid / CELLS_;
    int cp = tid % CELLS_;

    const float* feat; int g, l, noff, coff;
    if (cp < 361)        { feat = f0; g = 19; l = 0; noff = 0;    coff = 0;    }
    else if (cp < 1805)  { feat = f1; g = 38; l = 1; noff = 1083; coff = 361;  }
    else                 { feat = f2; g = 76; l = 2; noff = 5415; coff = 1805; }

    int cell = cp - coff;
    int gg = g * g;
    int gy = cell / g, gx = cell % g;

    // letterbox correction constants (input_shape = [608, 608])
    float imh = imshape[0], imw = imshape[1];
    const float ih = 608.0f, iw = 608.0f;
    float r  = fminf(ih/imh, iw/imw);
    float nh = rintf(imh*r), nw = rintf(imw*r);       // jnp.round = ties-to-even
    float offy = (ih - nh) * 0.5f / ih, offx = (iw - nw) * 0.5f / iw;
    float scy  = ih / nh,               scx  = iw / nw;

    const float* base[3];
    float conf[3];
    #pragma unroll
    for (int a = 0; a < 3; a++) {
        base[a] = feat + ((size_t)b*255 + a*85) * (size_t)gg + cell;
        float tx = base[a][0];
        float ty = base[a][(size_t)gg];
        float tw = base[a][2*(size_t)gg];
        float th = base[a][3*(size_t)gg];
        float to = base[a][4*(size_t)gg];
        conf[a] = sigmoidf_(to);

        float bx = (sigmoidf_(tx) + (float)gx) / (float)g;   // box_xy[...,0] / gh
        float by = (sigmoidf_(ty) + (float)gy) / (float)g;   // box_xy[...,1] / gw
        int aidx = (2 - l)*3 + a;                            // ANCHOR_MASK
        float bw = expf(tw) * anchors[aidx*2 + 0] / ih;      // box_wh[...,0] / input_shape[0]
        float bh = expf(th) * anchors[aidx*2 + 1] / iw;      // box_wh[...,1] / input_shape[1]

        // yolo_correct_boxes (yx / hw order)
        float y  = (by - offy) * scy;
        float x  = (bx - offx) * scx;
        float hh = bh * scy;
        float ww = bw * scx;

        int n = noff + cell*3 + a;
        float* ob = &g_boxes[((size_t)b*N_ + n)*4];
        ob[0] = (y - hh*0.5f) * imh;
        ob[1] = (x - ww*0.5f) * imw;
        ob[2] = (y + hh*0.5f) * imh;
        ob[3] = (x + ww*0.5f) * imw;
    }

    int n0 = noff + cell*3;
    size_t sb = (size_t)b*C_*N_ + n0;
    for (int c = 0; c < C_; c++) {
        size_t chan = (size_t)(5 + c) * gg;
        float s0 = conf[0] * sigmoidf_(base[0][chan]);
        float s1 = conf[1] * sigmoidf_(base[1][chan]);
        float s2 = conf[2] * sigmoidf_(base[2][chan]);
        float* sp = &g_scores[sb + (size_t)c*N_];
        sp[0] = s0; sp[1] = s1; sp[2] = s2;
    }
}

// ---------------- shared helpers: radix-select + bitonic sort ---------------
__device__ void bitonic128_desc(unsigned long long* sv) {
    int tid = threadIdx.x;
    for (int k = 2; k <= 128; k <<= 1) {
        for (int j = k >> 1; j > 0; j >>= 1) {
            __syncthreads();
            if (tid < 128) {
                int ixj = tid ^ j;
                if (ixj > tid) {
                    unsigned long long a = sv[tid], b = sv[ixj];
                    bool up = ((tid & k) == 0);
                    if (up ? (a < b) : (a > b)) { sv[tid] = b; sv[ixj] = a; }
                }
            }
        }
    }
    __syncthreads();
}

// Selects the exact top-100 of keys[0..n) with jax.lax.top_k tie semantics
// (value desc, index asc). Result: sv[0..99] = (key<<32) | (0xFFFFFFFF - idx),
// sorted descending. Requires blockDim.x >= 128.
__device__ void select_top_sorted(const uint32_t* __restrict__ keys, int n,
                                  int* hist, int* scnt, unsigned long long* sv) {
    int tid = threadIdx.x;
    uint32_t prefix = 0;
    int Krem = K_;
    int cntEq = 0;

    // 4-pass 8-bit radix select for the 100th-largest key
    for (int shift = 24; shift >= 0; shift -= 8) {
        __syncthreads();
        for (int i = tid; i < 256; i += blockDim.x) hist[i] = 0;
        __syncthreads();
        uint32_t hmask = (shift == 24) ? 0u : (0xFFFFFFFFu << (shift + 8));
        for (int i = tid; i < n; i += blockDim.x) {
            uint32_t k = keys[i];
            if ((k & hmask) == prefix) atomicAdd(&hist[(k >> shift) & 0xFFu], 1);
        }
        __syncthreads();
        if (tid == 0) {
            int cum = 0, d = 255;
            for (; d > 0; d--) {
                if (cum + hist[d] >= Krem) break;
                cum += hist[d];
            }
            scnt[0] = d;
            scnt[1] = Krem - cum;
            scnt[2] = hist[d];
        }
        __syncthreads();
        int d = scnt[0];
        Krem  = scnt[1];
        cntEq = scnt[2];
        prefix |= ((uint32_t)d) << shift;
    }

    uint32_t v = prefix;      // 100th largest key value
    int needed = Krem;        // how many ties at v to take (ascending index)
    int t = n - 1;            // index threshold among equals
    if (cntEq != needed) {    // duplicates at v: binary-search the index cutoff
        int lo = 0, hi = n - 1;
        while (lo < hi) {
            int mid = (lo + hi) >> 1;
            __syncthreads();
            if (tid == 0) scnt[0] = 0;
            __syncthreads();
            int c = 0;
            for (int i = tid; i <= mid; i += blockDim.x) c += (keys[i] == v) ? 1 : 0;
            if (c) atomicAdd(&scnt[0], c);
            __syncthreads();
            int cnt = scnt[0];
            __syncthreads();
            if (cnt >= needed) hi = mid; else lo = mid + 1;
        }
        t = lo;
    }

    // collect exactly 100 entries
    __syncthreads();
    if (tid == 0) scnt[0] = 0;
    __syncthreads();
    for (int i = tid; i < n; i += blockDim.x) {
        uint32_t k = keys[i];
        if (k > v || (k == v && i <= t)) {
            int p = atomicAdd(&scnt[0], 1);
            if (p < K_)
                sv[p] = (((unsigned long long)k) << 32)
                      | (unsigned long long)(0xFFFFFFFFu - (uint32_t)i);
        }
    }
    __syncthreads();
    if (tid >= K_ && tid < 128) sv[tid] = 0ULL;   // pad
    bitonic128_desc(sv);
}

// ---------------- stage 2: per-(b,c) top-100 --------------------------------
__global__ void topk_kernel() {
    extern __shared__ uint32_t skeys[];            // N_ * 4 bytes
    __shared__ int hist[256];
    __shared__ int scnt[4];
    __shared__ unsigned long long sv[128];

    int blk = blockIdx.x;                          // b*C_ + c
    const float* src = g_scores + (size_t)blk * N_;
    for (int i = threadIdx.x; i < N_; i += blockDim.x)
        skeys[i] = __float_as_uint(src[i]);        // scores > 0 -> bit order == float order
    __syncthreads();

    select_top_sorted(skeys, N_, hist, scnt, sv);

    if (threadIdx.x < K_) {
        unsigned long long s = sv[threadIdx.x];
        uint32_t k = (uint32_t)(s >> 32);
        int idx = (int)(0xFFFFFFFFu - (uint32_t)s);
        int b = blk / C_;
        g_top_s[(size_t)blk*K_ + threadIdx.x] = __uint_as_float(k);
        const float* bx = &g_boxes[((size_t)b*N_ + idx)*4];
        float* ob = &g_top_b[((size_t)blk*K_ + threadIdx.x)*4];
        ob[0] = bx[0]; ob[1] = bx[1]; ob[2] = bx[2]; ob[3] = bx[3];
    }
}

// ---------------- stage 3: greedy NMS per (b,c) -----------------------------
__global__ void nms_kernel() {
    __shared__ float y1s[K_], x1s[K_], y2s[K_], x2s[K_], ars[K_], scs[K_];
    __shared__ unsigned char vld[K_], sup[K_];
    int blk = blockIdx.x;
    int tid = threadIdx.x;

    if (tid < K_) {
        const float* bx = &g_top_b[((size_t)blk*K_ + tid)*4];
        float a0 = bx[0], a1 = bx[1], a2 = bx[2], a3 = bx[3];
        y1s[tid] = a0; x1s[tid] = a1; y2s[tid] = a2; x2s[tid] = a3;
        ars[tid] = fmaxf(a2 - a0, 0.f) * fmaxf(a3 - a1, 0.f);
        float s = g_top_s[(size_t)blk*K_ + tid];
        scs[tid] = s;
        vld[tid] = (s >= 0.2f) ? 1 : 0;
        sup[tid] = 0;
    }
    __syncthreads();

    for (int i = 0; i < K_; i++) {
        bool keep_i = vld[i] && !sup[i];
        if (keep_i && tid > i && tid < K_) {
            float iy1 = fmaxf(y1s[i], y1s[tid]);
            float ix1 = fmaxf(x1s[i], x1s[tid]);
            float iy2 = fminf(y2s[i], y2s[tid]);
            float ix2 = fminf(x2s[i], x2s[tid]);
            float inter = fmaxf(iy2 - iy1, 0.f) * fmaxf(ix2 - ix1, 0.f);
            float iou = inter / (ars[i] + ars[tid] - inter + 1e-9f);
            if (iou > 0.3f) sup[tid] = 1;
        }
        __syncthreads();
    }

    if (tid < K_)
        g_cand[(size_t)blk*K_ + tid] = (vld[tid] && !sup[tid]) ? scs[tid] : -1.0f;
}

// ---------------- stage 4: per-image top-100 over 8000 candidates -----------
__global__ void final_kernel(float* __restrict__ out) {
    __shared__ uint32_t skeys[M_];                 // 32 KB
    __shared__ int hist[256];
    __shared__ int scnt[4];
    __shared__ unsigned long long sv[128];

    int b = blockIdx.x;
    const float* src = g_cand + (size_t)b * M_;
    for (int i = threadIdx.x; i < M_; i += blockDim.x) {
        uint32_t u = __float_as_uint(src[i]);      // values may be -1.0
        skeys[i] = (u & 0x80000000u) ? ~u : (u | 0x80000000u);  // monotone map
    }
    __syncthreads();

    select_top_sorted(skeys, M_, hist, scnt, sv);

    if (threadIdx.x < K_) {
        unsigned long long s = sv[threadIdx.x];
        int idx = (int)(0xFFFFFFFFu - (uint32_t)s); // flat c*100+rank index
        const float* bx = &g_top_b[((size_t)b*M_ + idx)*4];
        float val = g_cand[(size_t)b*M_ + idx];
        float* o = out + ((size_t)b*K_ + threadIdx.x)*6;
        o[0] = bx[0]; o[1] = bx[1]; o[2] = bx[2]; o[3] = bx[3];
        o[4] = val;
        o[5] = (float)(idx / K_);
    }
}

// ---------------- launch -----------------------------------------------------
extern "C" void kernel_launch(void* const* d_in, const int* in_sizes, int n_in,
                              void* d_out, int out_size) {
    const float* f0      = (const float*)d_in[0];
    const float* f1      = (const float*)d_in[1];
    const float* f2      = (const float*)d_in[2];
    const float* anchors = (const float*)d_in[3];
    const float* imshape = (const float*)d_in[4];
    float* out = (float*)d_out;

    cudaFuncSetAttribute(topk_kernel, cudaFuncAttributeMaxDynamicSharedMemorySize,
                         N_ * (int)sizeof(uint32_t));

    int total = B_ * CELLS_;
    decode_kernel<<<(total + 255) / 256, 256>>>(f0, f1, f2, anchors, imshape);
    topk_kernel<<<B_*C_, 256, N_ * sizeof(uint32_t)>>>();
    nms_kernel<<<B_*C_, 128>>>();
    final_kernel<<<B_, 256>>>(out);
}